// round 1
// baseline (speedup 1.0000x reference)
#include <cuda_runtime.h>
#include <cstdint>

// WinnerTakesAll: per-batch top-64 mask.
// x: (32, 32, 256, 256) fp32 -> B=32 batches of N=2^21 elements.
// out[i] = x[i] if x[i] is among the 64 largest of its batch (ties: lower index), else 0.
//
// Strategy (1 full read + 1 full write of HBM):
//   Z: zero output (256 MiB write)
//   A: per-block exact top-64 (one DRAM read pass + one L2-resident re-read pass)
//   E: per-batch merge of 64 blocks x 64 candidates -> scatter 64 winners.

#define BATCHES 32
#define N_PER   2097152            // 32*256*256
#define BPB     64                 // blocks per batch
#define CHUNK   (N_PER / BPB)      // 32768 elements = 128 KiB
#define TPB_A   512
#define VPT     (CHUNK / 4 / TPB_A)  // 16 float4 per thread
#define CAP     512                // candidate capacity per block (E[ncand] ~ 68)
#define S2_PER_BLOCK 64
#define S2_TOTAL (BPB * S2_PER_BLOCK)   // 4096 candidates per batch

// Stage-2 candidate buffer: fully overwritten every launch (deterministic).
__device__ unsigned long long g_s2[BATCHES][S2_TOTAL];

__device__ __forceinline__ unsigned key32(float v) {
    unsigned u = __float_as_uint(v);
    return (u & 0x80000000u) ? ~u : (u | 0x80000000u);  // monotone order-preserving
}

__device__ __forceinline__ float neg_inf() {
    return __int_as_float(0xff800000);
}

// ---------------------------------------------------------------------------
// Kernel Z: zero the output (output is poisoned before timing).
// ---------------------------------------------------------------------------
__global__ void zero_kernel(float4* __restrict__ out, int n4) {
    int i = blockIdx.x * blockDim.x + threadIdx.x;
    int stride = gridDim.x * blockDim.x;
    float4 z = make_float4(0.f, 0.f, 0.f, 0.f);
    for (; i < n4; i += stride) out[i] = z;
}

// ---------------------------------------------------------------------------
// Kernel A: per-block exact top-64.
//   Pass 1: thread-max over 64 elems; sort 512 thread-maxes; P = 64th largest.
//           (>=64 threads have max >= P  =>  count(chunk >= P) >= 64
//            =>  block top-64 is a subset of {x >= P})
//   Pass 2: re-read chunk (L2-resident), collect candidates >= P, sort by
//           packed 64-bit key (value desc, index asc), emit top-64.
// ---------------------------------------------------------------------------
__global__ void __launch_bounds__(TPB_A)
topk_block_kernel(const float* __restrict__ x) {
    __shared__ float s_max[TPB_A];
    __shared__ unsigned long long s_c[CAP];
    __shared__ int s_cnt;
    __shared__ float s_P;

    const int t = threadIdx.x;
    const int batch = blockIdx.y;
    const int blk = blockIdx.x;
    const float4* __restrict__ x4 = (const float4*)x;
    const size_t base4 = (size_t)batch * (N_PER / 4) + (size_t)blk * (CHUNK / 4);

    // ---- Pass 1: thread-local max (streams chunk from DRAM) ----
    float tmax = neg_inf();
#pragma unroll
    for (int i = 0; i < VPT; i++) {
        float4 v = x4[base4 + (size_t)i * TPB_A + t];
        tmax = fmaxf(tmax, fmaxf(fmaxf(v.x, v.y), fmaxf(v.z, v.w)));
    }
    s_max[t] = tmax;
    __syncthreads();

    // Bitonic sort (descending) of 512 thread-maxes; P = s_max[63].
    for (int k = 2; k <= TPB_A; k <<= 1) {
        for (int j = k >> 1; j > 0; j >>= 1) {
            int l = t ^ j;
            if (l > t) {
                float a = s_max[t], b = s_max[l];
                bool dir = ((t & k) == 0);
                if (dir ? (a < b) : (a > b)) { s_max[t] = b; s_max[l] = a; }
            }
            __syncthreads();
        }
    }
    if (t == 0) { s_P = s_max[63]; s_cnt = 0; }
    s_c[t] = 0ull;  // CAP == TPB_A; pad value sorts below any real key
    __syncthreads();
    const float P = s_P;

    // ---- Pass 2: collect candidates >= P (re-read is L2-resident) ----
#pragma unroll
    for (int i = 0; i < VPT; i++) {
        float4 v = x4[base4 + (size_t)i * TPB_A + t];
        unsigned idx0 = (unsigned)(blk * CHUNK + (i * TPB_A + t) * 4);
        float vv[4] = {v.x, v.y, v.z, v.w};
#pragma unroll
        for (int c = 0; c < 4; c++) {
            if (vv[c] >= P) {
                int pos = atomicAdd(&s_cnt, 1);
                if (pos < CAP) {
                    unsigned long long sk =
                        ((unsigned long long)key32(vv[c]) << 32) |
                        (unsigned)(~(idx0 + (unsigned)c));
                    s_c[pos] = sk;
                }
            }
        }
    }
    __syncthreads();

    // Bitonic sort (descending) of 512 packed candidates.
    for (int k = 2; k <= CAP; k <<= 1) {
        for (int j = k >> 1; j > 0; j >>= 1) {
            int l = t ^ j;
            if (l > t) {
                unsigned long long a = s_c[t], b = s_c[l];
                bool dir = ((t & k) == 0);
                if (dir ? (a < b) : (a > b)) { s_c[t] = b; s_c[l] = a; }
            }
            __syncthreads();
        }
    }

    if (t < S2_PER_BLOCK)
        g_s2[batch][blk * S2_PER_BLOCK + t] = s_c[t];
}

// ---------------------------------------------------------------------------
// Kernel E: per-batch merge of 4096 candidates, scatter 64 winners.
// (Global top-64 is a subset of the union of block top-64 sets.)
// ---------------------------------------------------------------------------
#define TPB_E 512
__global__ void __launch_bounds__(TPB_E)
merge_kernel(const float* __restrict__ x, float* __restrict__ out) {
    __shared__ unsigned long long s_m[S2_TOTAL];  // 32 KiB
    const int t = threadIdx.x;
    const int batch = blockIdx.x;

    for (int i = t; i < S2_TOTAL; i += TPB_E) s_m[i] = g_s2[batch][i];
    __syncthreads();

    for (int k = 2; k <= S2_TOTAL; k <<= 1) {
        for (int j = k >> 1; j > 0; j >>= 1) {
            for (int i = t; i < S2_TOTAL; i += TPB_E) {
                int l = i ^ j;
                if (l > i) {
                    unsigned long long a = s_m[i], b = s_m[l];
                    bool dir = ((i & k) == 0);
                    if (dir ? (a < b) : (a > b)) { s_m[i] = b; s_m[l] = a; }
                }
            }
            __syncthreads();
        }
    }

    if (t < 64) {
        unsigned idx = ~((unsigned)s_m[t]);       // recover in-batch index
        size_t gi = (size_t)batch * N_PER + idx;
        out[gi] = x[gi];
    }
}

// ---------------------------------------------------------------------------
extern "C" void kernel_launch(void* const* d_in, const int* in_sizes, int n_in,
                              void* d_out, int out_size) {
    const float* x = (const float*)d_in[0];
    float* out = (float*)d_out;

    int n4 = out_size / 4;  // 8388608 float4
    zero_kernel<<<4096, 256>>>((float4*)out, n4);

    dim3 gA(BPB, BATCHES);
    topk_block_kernel<<<gA, TPB_A>>>(x);

    merge_kernel<<<BATCHES, TPB_E>>>(x, out);
}

// round 2
// speedup vs baseline: 1.6460x; 1.6460x over previous
#include <cuda_runtime.h>
#include <cstdint>

// WinnerTakesAll: per-batch top-64 mask. x: (32,32,256,256) fp32.
// B=32 batches, N=2^21 per batch. out = x on the 64 largest per batch
// (ties -> lower index), else 0.
//
// v2: ONE full DRAM read + ONE full DRAM write.
//  A: chunk in registers -> warp-shuffle threshold -> candidates to global,
//     then zero-write own output chunk (fuses the zero pass).
//  M: per-batch exact top-64 via bitwise threshold search (no sorting),
//     scatter 64 winners over the zeros.

#define BATCHES 32
#define N_PER   2097152
#define TPB_A   512
#define VPT4    16                         // float4 per thread
#define CHUNK   (TPB_A * VPT4 * 4)         // 32768 elements
#define BPB     (N_PER / CHUNK)            // 64 blocks per batch
#define CAP     8192                       // per-batch candidate capacity

__device__ unsigned long long g_cand[BATCHES][CAP];
__device__ int g_cnt[BATCHES];

__device__ __forceinline__ unsigned key32(float v) {
    unsigned u = __float_as_uint(v);
    return (u & 0x80000000u) ? ~u : (u | 0x80000000u);  // monotone
}

// ---------------------------------------------------------------------------
// Kernel A: one streaming read; per-block threshold; candidates out;
// zero-write own output chunk.
// ---------------------------------------------------------------------------
__global__ void __launch_bounds__(TPB_A, 1)
select_kernel(const float4* __restrict__ x4, float4* __restrict__ out4) {
    __shared__ float s_pool[128];   // 16 warps x top-8 thread-maxes
    __shared__ float s_P;

    const int t = threadIdx.x;
    const int lane = t & 31;
    const int warp = t >> 5;
    const int batch = blockIdx.y;
    const int blk = blockIdx.x;
    const size_t base4 = (size_t)batch * (N_PER / 4) + (size_t)blk * (CHUNK / 4);

    // ---- Load 64 elements into registers; compute thread max ----
    float4 v[VPT4];
#pragma unroll
    for (int i = 0; i < VPT4; i++)
        v[i] = x4[base4 + (size_t)i * TPB_A + t];

    float tmax = __int_as_float(0xff800000);
#pragma unroll
    for (int i = 0; i < VPT4; i++)
        tmax = fmaxf(tmax, fmaxf(fmaxf(v[i].x, v[i].y), fmaxf(v[i].z, v[i].w)));

    // ---- Warp-level bitonic sort (descending) of 32 thread-maxes ----
    float s = tmax;
#pragma unroll
    for (int k = 2; k <= 32; k <<= 1) {
#pragma unroll
        for (int j = k >> 1; j > 0; j >>= 1) {
            float o = __shfl_xor_sync(0xffffffffu, s, j);
            bool up = ((lane & k) == 0);
            bool lower = ((lane & j) == 0);
            s = (up == lower) ? fmaxf(s, o) : fminf(s, o);  // descending
        }
    }
    if (lane < 8) s_pool[warp * 8 + lane] = s;   // warp's top-8, desc
    __syncthreads();

    // ---- P = 64th largest of the 128-entry pool (exact rank, tie by idx) ----
    // >=64 pool entries (distinct thread maxes) >= P  =>  count(chunk >= P) >= 64
    // =>  block's exact top-64 all satisfy x >= P.
    if (t < 128) {
        float p = s_pool[t];
        int r = 0;
        for (int j = 0; j < 128; j++) {
            float pj = s_pool[j];
            r += (pj > p) || (pj == p && j < t);
        }
        if (r == 63) s_P = p;
    }
    __syncthreads();
    const float P = s_P;

    // ---- Candidate scan from registers (ballot-aggregated global writes) ----
#pragma unroll
    for (int i = 0; i < VPT4; i++) {
        float vv[4] = {v[i].x, v[i].y, v[i].z, v[i].w};
#pragma unroll
        for (int c = 0; c < 4; c++) {
            bool pred = (vv[c] >= P);
            unsigned m = __ballot_sync(0xffffffffu, pred);
            if (m) {
                int leader = __ffs(m) - 1;
                int pos = 0;
                if (lane == leader)
                    pos = atomicAdd(&g_cnt[batch], __popc(m));
                pos = __shfl_sync(0xffffffffu, pos, leader);
                if (pred) {
                    int my = pos + __popc(m & ((1u << lane) - 1u));
                    if (my < CAP) {
                        unsigned e = (unsigned)(blk * CHUNK + (i * TPB_A + t) * 4 + c);
                        g_cand[batch][my] =
                            ((unsigned long long)key32(vv[c]) << 32) | (unsigned)(~e);
                    }
                }
            }
        }
    }

    // ---- Zero-write this block's output chunk (replaces zero kernel) ----
    float4 z = make_float4(0.f, 0.f, 0.f, 0.f);
#pragma unroll
    for (int i = 0; i < VPT4; i++)
        out4[base4 + (size_t)i * TPB_A + t] = z;
}

// ---------------------------------------------------------------------------
// Kernel M: per-batch exact top-64 from candidates; scatter winners.
// ---------------------------------------------------------------------------
#define TPB_M 512
#define MAXS  512
__global__ void __launch_bounds__(TPB_M)
merge_kernel(const float* __restrict__ x, float* __restrict__ out) {
    __shared__ unsigned s_vk[CAP];               // 32 KiB value keys
    __shared__ unsigned long long s_surv[MAXS];  // 4 KiB survivors
    __shared__ int s_red[16];
    __shared__ int s_count;
    __shared__ int s_scnt;

    const int t = threadIdx.x;
    const int lane = t & 31;
    const int warp = t >> 5;
    const int batch = blockIdx.x;

    const int cnt = min(g_cnt[batch], CAP);
    for (int i = t; i < cnt; i += TPB_M)
        s_vk[i] = (unsigned)(g_cand[batch][i] >> 32);
    if (t == 0) s_scnt = 0;
    __syncthreads();

    // Largest T (32-bit key) with count(vk >= T) >= 64, built MSB->LSB.
    unsigned T = 0;
    for (int bit = 31; bit >= 0; bit--) {
        unsigned cand = T | (1u << bit);
        int c = 0;
        for (int i = t; i < cnt; i += TPB_M) c += (s_vk[i] >= cand);
#pragma unroll
        for (int o = 16; o > 0; o >>= 1) c += __shfl_xor_sync(0xffffffffu, c, o);
        if (lane == 0) s_red[warp] = c;
        __syncthreads();
        if (t == 0) {
            int tot = 0;
            for (int w = 0; w < 16; w++) tot += s_red[w];
            s_count = tot;
        }
        __syncthreads();
        if (s_count >= 64) T = cand;
    }

    // Compact survivors (vk >= T): ~64 of them (plus exact-value ties).
    for (int i = t; i < cnt; i += TPB_M) {
        if (s_vk[i] >= T) {
            int p = atomicAdd(&s_scnt, 1);
            if (p < MAXS) s_surv[p] = g_cand[batch][i];
        }
    }
    __syncthreads();
    const int S = min(s_scnt, MAXS);

    // Exact rank on packed key (value desc, index asc); winners rank < 64.
    if (t < S) {
        unsigned long long me = s_surv[t];
        int r = 0;
        for (int j = 0; j < S; j++) r += (s_surv[j] > me);
        if (r < 64) {
            unsigned idx = ~((unsigned)me);
            size_t gi = (size_t)batch * N_PER + idx;
            out[gi] = x[gi];
        }
    }
}

// ---------------------------------------------------------------------------
extern "C" void kernel_launch(void* const* d_in, const int* in_sizes, int n_in,
                              void* d_out, int out_size) {
    const float* x = (const float*)d_in[0];
    float* out = (float*)d_out;

    void* cnt_ptr = nullptr;
    cudaGetSymbolAddress(&cnt_ptr, g_cnt);
    cudaMemsetAsync(cnt_ptr, 0, sizeof(int) * BATCHES, 0);

    dim3 gA(BPB, BATCHES);
    select_kernel<<<gA, TPB_A>>>((const float4*)x, (float4*)out);

    merge_kernel<<<BATCHES, TPB_M>>>(x, out);
}